// round 2
// baseline (speedup 1.0000x reference)
#include <cuda_runtime.h>
#include <math.h>

#define DIM 512
#define NN 50000
#define NE 100000
#define TOTE (2*NE)
#define NRELS 4
#define FFDIM 1024

// ---------------- scratch (device globals; no allocation allowed) -------------
__device__ float g_base[NN*DIM];            // 102.4 MB  LN(input) ("base")
__device__ float g_s[NRELS*NN*DIM];         // 409.6 MB  per-rel weighted scatter sums
__device__ float g_deg[NRELS*NN];           // per-rel weighted degree
__device__ float g_agg[NN*DIM];             // agg / also reused as FFN2 output
__device__ float g_x1[NN*DIM];              // post-LN1 activations
__device__ float g_u[NN*FFDIM];             // FFN hidden
__device__ float g_part[256*DIM];           // pooling partials
__device__ int   g_is64;                    // 1 if index inputs are int64

// ---------------- index dtype detection --------------------------------------
// If indices are int64 (values < 2^31), every odd 32-bit word of edge_index is 0.
// With int32 random indices in [0,50000), that is impossible over 100000 words.
__global__ void detect_idx_kernel(const unsigned int* __restrict__ w) {
    __shared__ int nz;
    if (threadIdx.x == 0) nz = 0;
    __syncthreads();
    int found = 0;
    for (int i = threadIdx.x; i < TOTE/2 * 2; i += blockDim.x) {
        // check odd words among the first 2*NE int32 words (safe for both layouts)
        if (w[2*i + 1] != 0u) { found = 1; break; }
        if (2*i + 1 >= TOTE - 1) break;
    }
    if (found) atomicOr(&nz, 1);
    __syncthreads();
    if (threadIdx.x == 0) g_is64 = nz ? 0 : 1;
}

__device__ __forceinline__ int ldidx(const void* p, long long i) {
    return g_is64 ? (int)((const long long*)p)[i] : ((const int*)p)[i];
}

// ---------------- zero scratch ------------------------------------------------
__global__ void zero_kernel() {
    long long n4 = (long long)NRELS*NN*DIM/4;
    float4* s4 = (float4*)g_s;
    float4 z = make_float4(0.f,0.f,0.f,0.f);
    long long stride = (long long)gridDim.x * blockDim.x;
    for (long long i = (long long)blockIdx.x*blockDim.x + threadIdx.x; i < n4; i += stride)
        s4[i] = z;
    for (int i = blockIdx.x*blockDim.x + threadIdx.x; i < NRELS*NN; i += (int)stride)
        g_deg[i] = 0.f;
}

// ---------------- input LayerNorm: base = LN(nf + emb[ntype]) -----------------
__global__ void input_ln_kernel(const float* __restrict__ nf, const void* __restrict__ ntype,
                                const float* __restrict__ emb, const float* __restrict__ gw,
                                const float* __restrict__ gb) {
    __shared__ float2 red[256];
    int row = blockIdx.x, t = threadIdx.x;
    int nt = ldidx(ntype, row);
    long long off = (long long)row * DIM;
    float v0 = nf[off + t]       + emb[nt*DIM + t];
    float v1 = nf[off + t + 256] + emb[nt*DIM + t + 256];
    red[t] = make_float2(v0 + v1, v0*v0 + v1*v1);
    __syncthreads();
    for (int s = 128; s > 0; s >>= 1) {
        if (t < s) { red[t].x += red[t+s].x; red[t].y += red[t+s].y; }
        __syncthreads();
    }
    float m = red[0].x * (1.f/DIM);
    float var = red[0].y * (1.f/DIM) - m*m;
    float r = rsqrtf(var + 1e-5f);
    g_base[off + t]       = (v0 - m)*r*gw[t]     + gb[t];
    g_base[off + t + 256] = (v1 - m)*r*gw[t+256] + gb[t+256];
}

// ---------------- edge scatter: s[rel][dst] += w * base[src]; deg[rel][dst] += w
__global__ void scatter_kernel(const void* __restrict__ ei, const void* __restrict__ et,
                               const float* __restrict__ ew) {
    int e = blockIdx.x;         // 0 .. 2E-1
    int t = threadIdx.x;        // 0 .. 511
    int src, dst, rel; float w;
    if (e < NE) {
        src = ldidx(ei, e); dst = ldidx(ei, NE + e);
        rel = ldidx(et, e); w = ew[e];
    } else {
        int e2 = e - NE;
        src = ldidx(ei, NE + e2); dst = ldidx(ei, e2);
        rel = ldidx(et, e2) + 2;  w = ew[e2];
    }
    float v = w * g_base[(long long)src*DIM + t];
    atomicAdd(&g_s[((long long)rel*NN + dst)*DIM + t], v);
    if (t == 0) atomicAdd(&g_deg[rel*NN + dst], w);
}

// ---------------- SGEMM (NT): C[m,n] (+)= sum_b sum_k A_b[m,k]*B_b[n,k] -------
#define BM 128
#define BN 128
#define BK 16
#define TM 8
#define TN 8

__global__ void __launch_bounds__(256) sgemm_nt(
    const float* __restrict__ A, const float* __restrict__ B, float* __restrict__ C,
    int M, int N, int K, int nb, long long sA, long long sB, int accum)
{
    __shared__ float As[BK][BM+4];
    __shared__ float Bs[BK][BN+4];
    int tid = threadIdx.x;
    int bm = blockIdx.y * BM;
    int bn = blockIdx.x * BN;
    int ty = tid >> 4, tx = tid & 15;
    float acc[TM][TN];
    #pragma unroll
    for (int i = 0; i < TM; i++)
        #pragma unroll
        for (int j = 0; j < TN; j++) acc[i][j] = 0.f;

    for (int b = 0; b < nb; ++b) {
        const float* Ab = A + (long long)b * sA;
        const float* Bb = B + (long long)b * sB;
        for (int k0 = 0; k0 < K; k0 += BK) {
            __syncthreads();
            #pragma unroll
            for (int l = 0; l < 2; ++l) {
                int f = tid + l*256;
                int r = f >> 2;
                int c4 = (f & 3) << 2;
                int gr = bm + r;
                float4 v = make_float4(0.f,0.f,0.f,0.f);
                if (gr < M) v = *(const float4*)(Ab + (long long)gr*K + k0 + c4);
                As[c4+0][r] = v.x; As[c4+1][r] = v.y; As[c4+2][r] = v.z; As[c4+3][r] = v.w;
            }
            #pragma unroll
            for (int l = 0; l < 2; ++l) {
                int f = tid + l*256;
                int r = f >> 2;
                int c4 = (f & 3) << 2;
                float4 v = *(const float4*)(Bb + (long long)(bn + r)*K + k0 + c4);
                Bs[c4+0][r] = v.x; Bs[c4+1][r] = v.y; Bs[c4+2][r] = v.z; Bs[c4+3][r] = v.w;
            }
            __syncthreads();
            #pragma unroll
            for (int kk = 0; kk < BK; ++kk) {
                float ra[TM], rb[TN];
                *(float4*)&ra[0] = *(const float4*)&As[kk][ty*TM];
                *(float4*)&ra[4] = *(const float4*)&As[kk][ty*TM + 4];
                *(float4*)&rb[0] = *(const float4*)&Bs[kk][tx*TN];
                *(float4*)&rb[4] = *(const float4*)&Bs[kk][tx*TN + 4];
                #pragma unroll
                for (int i = 0; i < TM; i++)
                    #pragma unroll
                    for (int j = 0; j < TN; j++)
                        acc[i][j] += ra[i] * rb[j];
            }
        }
    }
    #pragma unroll
    for (int i = 0; i < TM; i++) {
        int gr = bm + ty*TM + i;
        if (gr < M) {
            float* Cp = C + (long long)gr*N + bn + tx*TN;
            if (accum) {
                #pragma unroll
                for (int j = 0; j < TN; j++) Cp[j] += acc[i][j];
            } else {
                *(float4*)&Cp[0] = *(const float4*)&acc[i][0];
                *(float4*)&Cp[4] = *(const float4*)&acc[i][4];
            }
        }
    }
}

// ---------------- agg finalize: agg = (agg + sum_r deg_r*b_rel[r]) / max(deg,1)
__global__ void agg_fin_kernel(const float* __restrict__ b_rel) {
    long long n = (long long)NN * DIM;
    long long stride = (long long)gridDim.x * blockDim.x;
    for (long long idx = (long long)blockIdx.x*blockDim.x + threadIdx.x; idx < n; idx += stride) {
        int row = (int)(idx >> 9);
        int col = (int)(idx & 511);
        float d0 = g_deg[row], d1 = g_deg[NN + row], d2 = g_deg[2*NN + row], d3 = g_deg[3*NN + row];
        float dsum = d0 + d1 + d2 + d3;
        float inv = 1.f / fmaxf(dsum, 1.f);
        float v = g_agg[idx] + d0*b_rel[col] + d1*b_rel[DIM + col]
                             + d2*b_rel[2*DIM + col] + d3*b_rel[3*DIM + col];
        g_agg[idx] = v * inv;
    }
}

// ---------------- LN1: x1 = LN(base + (agg + base@Wself) + b_self) ------------
__global__ void ln1_kernel(const float* __restrict__ b_self, const float* __restrict__ gw,
                           const float* __restrict__ gb) {
    __shared__ float2 red[256];
    int row = blockIdx.x, t = threadIdx.x;
    long long off = (long long)row * DIM;
    float v0 = g_base[off+t]     + g_agg[off+t]     + b_self[t];
    float v1 = g_base[off+t+256] + g_agg[off+t+256] + b_self[t+256];
    red[t] = make_float2(v0 + v1, v0*v0 + v1*v1);
    __syncthreads();
    for (int s = 128; s > 0; s >>= 1) {
        if (t < s) { red[t].x += red[t+s].x; red[t].y += red[t+s].y; }
        __syncthreads();
    }
    float m = red[0].x * (1.f/DIM);
    float var = red[0].y * (1.f/DIM) - m*m;
    float r = rsqrtf(var + 1e-5f);
    g_x1[off+t]     = (v0 - m)*r*gw[t]     + gb[t];
    g_x1[off+t+256] = (v1 - m)*r*gw[t+256] + gb[t+256];
}

// ---------------- GELU (exact) on FFN hidden ----------------------------------
__global__ void gelu_kernel(const float* __restrict__ bf1) {
    long long n = (long long)NN * FFDIM;
    long long stride = (long long)gridDim.x * blockDim.x;
    for (long long idx = (long long)blockIdx.x*blockDim.x + threadIdx.x; idx < n; idx += stride) {
        int col = (int)(idx & (FFDIM-1));
        float v = g_u[idx] + bf1[col];
        g_u[idx] = 0.5f * v * (1.f + erff(v * 0.70710678118654752f));
    }
}

// ---------------- final fused: LN2 -> out-LN -> graph mix -> write x ----------
__global__ void final_fuse_kernel(const float* __restrict__ bf2,
                                  const float* __restrict__ n2g, const float* __restrict__ n2b,
                                  const float* __restrict__ og,  const float* __restrict__ ob,
                                  const float* __restrict__ gml, float* __restrict__ out) {
    __shared__ float2 red[256];
    int row = blockIdx.x, t = threadIdx.x;
    long long off = (long long)row * DIM;
    // t = x1 + ffn_out + bf2  (g_agg holds FFN2 output)
    float t0 = g_x1[off+t]     + g_agg[off+t]     + bf2[t];
    float t1 = g_x1[off+t+256] + g_agg[off+t+256] + bf2[t+256];
    // LN (n2)
    red[t] = make_float2(t0 + t1, t0*t0 + t1*t1);
    __syncthreads();
    for (int s = 128; s > 0; s >>= 1) {
        if (t < s) { red[t].x += red[t+s].x; red[t].y += red[t+s].y; }
        __syncthreads();
    }
    float m = red[0].x * (1.f/DIM);
    float var = red[0].y * (1.f/DIM) - m*m;
    float r = rsqrtf(var + 1e-5f);
    float x20 = (t0 - m)*r*n2g[t]     + n2b[t];
    float x21 = (t1 - m)*r*n2g[t+256] + n2b[t+256];
    __syncthreads();
    // LN (out)
    red[t] = make_float2(x20 + x21, x20*x20 + x21*x21);
    __syncthreads();
    for (int s = 128; s > 0; s >>= 1) {
        if (t < s) { red[t].x += red[t+s].x; red[t].y += red[t+s].y; }
        __syncthreads();
    }
    m = red[0].x * (1.f/DIM);
    var = red[0].y * (1.f/DIM) - m*m;
    r = rsqrtf(var + 1e-5f);
    float x30 = (x20 - m)*r*og[t]     + ob[t];
    float x31 = (x21 - m)*r*og[t+256] + ob[t+256];
    float gm = 1.f / (1.f + expf(-gml[0]));
    float b0 = g_base[off+t], b1 = g_base[off+t+256];
    out[off+t]     = b0 + gm*(x30 - b0);
    out[off+t+256] = b1 + gm*(x31 - b1);
}

// ---------------- pooling -----------------------------------------------------
__global__ void pool_part_kernel(const float* __restrict__ x) {
    int b = blockIdx.x;       // 0..255
    int t = threadIdx.x;      // 0..511 (column)
    float s = 0.f;
    for (int r = b; r < NN; r += 256)
        s += x[(long long)r*DIM + t];
    g_part[b*DIM + t] = s;
}

__global__ void pool_final_kernel(const float* __restrict__ x, const float* __restrict__ dml,
                                  float* __restrict__ pooled) {
    int t = threadIdx.x;      // 0..511
    float s = 0.f;
    for (int b = 0; b < 256; ++b) s += g_part[b*DIM + t];
    float mean = s * (1.f / NN);
    float dm = 1.f / (1.f + expf(-dml[0]));
    pooled[t] = dm * x[t] + (1.f - dm) * mean;
}

// ---------------- host launcher ----------------------------------------------
extern "C" void kernel_launch(void* const* d_in, const int* in_sizes, int n_in,
                              void* d_out, int out_size) {
    (void)in_sizes; (void)n_in; (void)out_size;
    const float* nf     = (const float*)d_in[0];
    const void*  ei     = d_in[1];
    const void*  et     = d_in[2];
    const void*  ntype  = d_in[3];
    const float* ew     = (const float*)d_in[4];
    const float* emb    = (const float*)d_in[5];
    const float* W_self = (const float*)d_in[6];
    const float* b_self = (const float*)d_in[7];
    const float* W_rel  = (const float*)d_in[8];
    const float* b_rel  = (const float*)d_in[9];
    const float* in_g   = (const float*)d_in[10];
    const float* in_b   = (const float*)d_in[11];
    const float* n1_g   = (const float*)d_in[12];
    const float* n1_b   = (const float*)d_in[13];
    const float* Wf1    = (const float*)d_in[14];
    const float* bf1    = (const float*)d_in[15];
    const float* Wf2    = (const float*)d_in[16];
    const float* bf2    = (const float*)d_in[17];
    const float* n2_g   = (const float*)d_in[18];
    const float* n2_b   = (const float*)d_in[19];
    const float* out_g  = (const float*)d_in[20];
    const float* out_b  = (const float*)d_in[21];
    const float* gml    = (const float*)d_in[22];
    const float* dml    = (const float*)d_in[23];
    float* out = (float*)d_out;

    static float *p_base = nullptr, *p_s, *p_agg, *p_x1, *p_u;
    if (!p_base) {
        cudaGetSymbolAddress((void**)&p_base, g_base);
        cudaGetSymbolAddress((void**)&p_s,    g_s);
        cudaGetSymbolAddress((void**)&p_agg,  g_agg);
        cudaGetSymbolAddress((void**)&p_x1,   g_x1);
        cudaGetSymbolAddress((void**)&p_u,    g_u);
    }

    const int MROWS = (NN + BM - 1) / BM;   // 391

    detect_idx_kernel<<<1, 256>>>((const unsigned int*)ei);
    zero_kernel<<<1184, 256>>>();
    input_ln_kernel<<<NN, 256>>>(nf, ntype, emb, in_g, in_b);
    scatter_kernel<<<TOTE, 512>>>(ei, et, ew);

    // agg = sum_r s_r @ W_rel[r].T
    {
        dim3 grid(DIM / BN, MROWS);
        sgemm_nt<<<grid, 256>>>(p_s, W_rel, p_agg, NN, DIM, DIM, NRELS,
                                (long long)NN*DIM, (long long)DIM*DIM, 0);
    }
    agg_fin_kernel<<<2048, 256>>>(b_rel);
    // agg += base @ W_self.T
    {
        dim3 grid(DIM / BN, MROWS);
        sgemm_nt<<<grid, 256>>>(p_base, W_self, p_agg, NN, DIM, DIM, 1, 0, 0, 1);
    }
    ln1_kernel<<<NN, 256>>>(b_self, n1_g, n1_b);

    // FFN
    {
        dim3 grid(FFDIM / BN, MROWS);
        sgemm_nt<<<grid, 256>>>(p_x1, Wf1, p_u, NN, FFDIM, DIM, 1, 0, 0, 0);
    }
    gelu_kernel<<<2048, 256>>>(bf1);
    {
        dim3 grid(DIM / BN, MROWS);
        sgemm_nt<<<grid, 256>>>(p_u, Wf2, p_agg, NN, DIM, FFDIM, 1, 0, 0, 0);
    }

    final_fuse_kernel<<<NN, 256>>>(bf2, n2_g, n2_b, out_g, out_b, gml, out);
    pool_part_kernel<<<256, 512>>>(out);
    pool_final_kernel<<<1, 512>>>(out, dml, out + (long long)NN*DIM);
}

// round 3
// speedup vs baseline: 1.8160x; 1.8160x over previous
#include <cuda_runtime.h>
#include <cuda_bf16.h>
#include <math.h>
#include <stdint.h>

#define DIM 512
#define NN 50000
#define NE 100000
#define TOTE (2*NE)
#define NRELS 4
#define FFDIM 1024

// ---------------- scratch (device globals; no allocation allowed) -------------
__device__ float g_s[NRELS*NN*DIM];             // 409.6 MB per-rel scatter sums (fp32 atomics)
__device__ __nv_bfloat16 g_sh[NRELS*NN*DIM];    // bf16 hi of s
__device__ __nv_bfloat16 g_sl[NRELS*NN*DIM];    // bf16 lo of s
__device__ float g_deg[NRELS*NN];
__device__ float g_base[NN*DIM];
__device__ __nv_bfloat16 g_baseh[NN*DIM];
__device__ __nv_bfloat16 g_basel[NN*DIM];
__device__ float g_agg[NN*DIM];                 // agg / reused as FFN2 output
__device__ float g_x1[NN*DIM];
__device__ __nv_bfloat16 g_x1h[NN*DIM];
__device__ __nv_bfloat16 g_x1l[NN*DIM];
__device__ __nv_bfloat16 g_uh[NN*FFDIM];        // FFN hidden (post-gelu) hi
__device__ __nv_bfloat16 g_ul[NN*FFDIM];        // FFN hidden lo
#define NWELEM 2359296
#define WREL_OFF 0
#define WSELF_OFF 1048576
#define WF1_OFF 1310720
#define WF2_OFF 1835008
__device__ __nv_bfloat16 g_wh[NWELEM];
__device__ __nv_bfloat16 g_wl[NWELEM];
__device__ float g_part[256*DIM];
__device__ int   g_is64;

// ---------------- index dtype detection --------------------------------------
__global__ void detect_idx_kernel(const unsigned int* __restrict__ w) {
    __shared__ int nz;
    if (threadIdx.x == 0) nz = 0;
    __syncthreads();
    int found = 0;
    for (int i = threadIdx.x; i < TOTE/2 * 2; i += blockDim.x) {
        if (w[2*i + 1] != 0u) { found = 1; break; }
        if (2*i + 1 >= TOTE - 1) break;
    }
    if (found) atomicOr(&nz, 1);
    __syncthreads();
    if (threadIdx.x == 0) g_is64 = nz ? 0 : 1;
}

__device__ __forceinline__ int ldidx(const void* p, long long i) {
    return g_is64 ? (int)((const long long*)p)[i] : ((const int*)p)[i];
}

// ---------------- zero scratch ------------------------------------------------
__global__ void zero_kernel() {
    long long n4 = (long long)NRELS*NN*DIM/4;
    float4* s4 = (float4*)g_s;
    float4 z = make_float4(0.f,0.f,0.f,0.f);
    long long stride = (long long)gridDim.x * blockDim.x;
    for (long long i = (long long)blockIdx.x*blockDim.x + threadIdx.x; i < n4; i += stride)
        s4[i] = z;
    for (int i = blockIdx.x*blockDim.x + threadIdx.x; i < NRELS*NN; i += (int)stride)
        g_deg[i] = 0.f;
}

// ---------------- bf16 split helpers -----------------------------------------
__device__ __forceinline__ void split_bf16(float v, __nv_bfloat16& h, __nv_bfloat16& l) {
    h = __float2bfloat16(v);
    l = __float2bfloat16(v - __bfloat162float(h));
}

// ---------------- input LayerNorm: base = LN(nf + emb[ntype]) -----------------
__global__ void input_ln_kernel(const float* __restrict__ nf, const void* __restrict__ ntype,
                                const float* __restrict__ emb, const float* __restrict__ gw,
                                const float* __restrict__ gb) {
    __shared__ float2 red[256];
    int row = blockIdx.x, t = threadIdx.x;
    int nt = ldidx(ntype, row);
    long long off = (long long)row * DIM;
    float v0 = nf[off + t]       + emb[nt*DIM + t];
    float v1 = nf[off + t + 256] + emb[nt*DIM + t + 256];
    red[t] = make_float2(v0 + v1, v0*v0 + v1*v1);
    __syncthreads();
    for (int s = 128; s > 0; s >>= 1) {
        if (t < s) { red[t].x += red[t+s].x; red[t].y += red[t+s].y; }
        __syncthreads();
    }
    float m = red[0].x * (1.f/DIM);
    float var = red[0].y * (1.f/DIM) - m*m;
    float r = rsqrtf(var + 1e-5f);
    float b0 = (v0 - m)*r*gw[t]     + gb[t];
    float b1 = (v1 - m)*r*gw[t+256] + gb[t+256];
    g_base[off + t]       = b0;
    g_base[off + t + 256] = b1;
    split_bf16(b0, g_baseh[off+t],     g_basel[off+t]);
    split_bf16(b1, g_baseh[off+t+256], g_basel[off+t+256]);
}

// ---------------- edge scatter ------------------------------------------------
__global__ void scatter_kernel(const void* __restrict__ ei, const void* __restrict__ et,
                               const float* __restrict__ ew) {
    int e = blockIdx.x;
    int t = threadIdx.x;
    int src, dst, rel; float w;
    if (e < NE) {
        src = ldidx(ei, e); dst = ldidx(ei, NE + e);
        rel = ldidx(et, e); w = ew[e];
    } else {
        int e2 = e - NE;
        src = ldidx(ei, NE + e2); dst = ldidx(ei, e2);
        rel = ldidx(et, e2) + 2;  w = ew[e2];
    }
    float v = w * g_base[(long long)src*DIM + t];
    atomicAdd(&g_s[((long long)rel*NN + dst)*DIM + t], v);
    if (t == 0) atomicAdd(&g_deg[rel*NN + dst], w);
}

// ---------------- convert s -> bf16 hi/lo -------------------------------------
__global__ void conv_s_kernel() {
    long long n = (long long)NRELS*NN*DIM;
    long long stride = (long long)gridDim.x * blockDim.x;
    for (long long i = (long long)blockIdx.x*blockDim.x + threadIdx.x; i < n; i += stride)
        split_bf16(g_s[i], g_sh[i], g_sl[i]);
}

__global__ void conv_w_kernel(const float* __restrict__ src, int n, int off) {
    for (int i = blockIdx.x*blockDim.x + threadIdx.x; i < n; i += gridDim.x*blockDim.x)
        split_bf16(src[i], g_wh[off + i], g_wl[off + i]);
}

// ================= bf16-split tensor-core GEMM (NT) ===========================
// C[m,n] (+)= sum_b sum_k A_b[m,k]*B_b[n,k], fp32 via 3x bf16 mma (hi/lo split)
#define GBM 128
#define GBN 128
#define GBK 32

__device__ __forceinline__ void ldsm4(uint32_t* r, uint32_t addr) {
    asm volatile("ldmatrix.sync.aligned.m8n8.x4.shared.b16 {%0,%1,%2,%3},[%4];\n"
        : "=r"(r[0]), "=r"(r[1]), "=r"(r[2]), "=r"(r[3]) : "r"(addr));
}
__device__ __forceinline__ void mma_bf16(float* d, const uint32_t* a, uint32_t b0, uint32_t b1) {
    asm volatile("mma.sync.aligned.m16n8k16.row.col.f32.bf16.bf16.f32 "
        "{%0,%1,%2,%3},{%4,%5,%6,%7},{%8,%9},{%0,%1,%2,%3};\n"
        : "+f"(d[0]), "+f"(d[1]), "+f"(d[2]), "+f"(d[3])
        : "r"(a[0]), "r"(a[1]), "r"(a[2]), "r"(a[3]), "r"(b0), "r"(b1));
}
__device__ __forceinline__ void cp16(uint32_t dst, const void* src, int sz) {
    asm volatile("cp.async.cg.shared.global [%0],[%1],16,%2;\n" :: "r"(dst), "l"(src), "r"(sz));
}

// mode: 0 = store C, 1 = C += , 2 = gelu(acc+bias) -> (Oh,Ol) bf16 split
__global__ void __launch_bounds__(128) gemm_bf16s(
    const __nv_bfloat16* __restrict__ Ah, const __nv_bfloat16* __restrict__ Al,
    const __nv_bfloat16* __restrict__ Bh, const __nv_bfloat16* __restrict__ Bl,
    float* __restrict__ C,
    __nv_bfloat16* __restrict__ Oh, __nv_bfloat16* __restrict__ Ol,
    const float* __restrict__ bias,
    int M, int N, int K, int nb, long long sA, long long sB, int mode)
{
    extern __shared__ __align__(1024) char smraw[];
    const int tid = threadIdx.x;
    const int lane = tid & 31, wid = tid >> 5;
    const int wm = wid >> 1, wn = wid & 1;
    const int bm = blockIdx.y * GBM, bn = blockIdx.x * GBN;
    const int kiPerB = K / GBK;
    const int niter = nb * kiPerB;
    uint32_t smbase = (uint32_t)__cvta_generic_to_shared(smraw);

    float acc[4][8][4];
    #pragma unroll
    for (int i = 0; i < 4; i++)
        #pragma unroll
        for (int j = 0; j < 8; j++)
            #pragma unroll
            for (int c = 0; c < 4; c++) acc[i][j][c] = 0.f;

    // ---- async copy of one stage -------------------------------------------
    auto issue_copy = [&](int stage, int it) {
        int b  = it / kiPerB;
        int kb = (it - b * kiPerB) * GBK;
        const __nv_bfloat16* base0 = Ah + (long long)b * sA;
        const __nv_bfloat16* base1 = Al + (long long)b * sA;
        const __nv_bfloat16* base2 = Bh + (long long)b * sB;
        const __nv_bfloat16* base3 = Bl + (long long)b * sB;
        #pragma unroll
        for (int i = 0; i < 16; i++) {
            int id  = i * 128 + tid;
            int q   = id >> 9;
            int rem = id & 511;
            int row = rem >> 2, c = rem & 3;
            uint32_t dst = smbase + stage*32768 + q*8192
                         + (uint32_t)(row*64 + ((c ^ ((row>>1)&3)) << 4));
            int sz = 16;
            const __nv_bfloat16* src;
            if (q < 2) {
                int gr = bm + row;
                if (gr >= M) { sz = 0; gr = 0; }
                src = (q == 0 ? base0 : base1) + (long long)gr*K + kb + c*8;
            } else {
                int gr = bn + row;
                src = (q == 2 ? base2 : base3) + (long long)gr*K + kb + c*8;
            }
            cp16(dst, src, sz);
        }
        asm volatile("cp.async.commit_group;\n" ::: "memory");
    };

    issue_copy(0, 0);

    for (int it = 0; it < niter; ++it) {
        if (it + 1 < niter) {
            issue_copy((it + 1) & 1, it + 1);
            asm volatile("cp.async.wait_group 1;\n" ::: "memory");
        } else {
            asm volatile("cp.async.wait_group 0;\n" ::: "memory");
        }
        __syncthreads();

        uint32_t sAh = smbase + (it & 1)*32768;
        uint32_t sAl = sAh + 8192;
        uint32_t sBh = sAh + 16384;
        uint32_t sBl = sAh + 24576;
        int rsel = lane & 15;
        #pragma unroll
        for (int kk = 0; kk < 2; kk++) {
            int csel = kk*2 + (lane >> 4);
            uint32_t ah[4][4], al[4][4], bh[4][4], bl[4][4];
            #pragma unroll
            for (int mi = 0; mi < 4; mi++) {
                int row = wm*64 + mi*16 + rsel;
                uint32_t off = (uint32_t)(row*64 + ((csel ^ ((row>>1)&3)) << 4));
                ldsm4(ah[mi], sAh + off);
                ldsm4(al[mi], sAl + off);
            }
            #pragma unroll
            for (int p = 0; p < 4; p++) {
                int row = wn*64 + p*16 + rsel;
                uint32_t off = (uint32_t)(row*64 + ((csel ^ ((row>>1)&3)) << 4));
                ldsm4(bh[p], sBh + off);
                ldsm4(bl[p], sBl + off);
            }
            #pragma unroll
            for (int mi = 0; mi < 4; mi++)
                #pragma unroll
                for (int nj = 0; nj < 8; nj++) {
                    int p = nj >> 1, h = nj & 1;
                    mma_bf16(acc[mi][nj], ah[mi], bh[p][h], bh[p][2+h]);
                }
            #pragma unroll
            for (int mi = 0; mi < 4; mi++)
                #pragma unroll
                for (int nj = 0; nj < 8; nj++) {
                    int p = nj >> 1, h = nj & 1;
                    mma_bf16(acc[mi][nj], al[mi], bh[p][h], bh[p][2+h]);
                }
            #pragma unroll
            for (int mi = 0; mi < 4; mi++)
                #pragma unroll
                for (int nj = 0; nj < 8; nj++) {
                    int p = nj >> 1, h = nj & 1;
                    mma_bf16(acc[mi][nj], ah[mi], bl[p][h], bl[p][2+h]);
                }
        }
        __syncthreads();
    }

    // ---- epilogue -----------------------------------------------------------
    #pragma unroll
    for (int mi = 0; mi < 4; mi++) {
        #pragma unroll
        for (int nj = 0; nj < 8; nj++) {
            int gc = bn + wn*64 + nj*8 + (lane & 3)*2;
            #pragma unroll
            for (int half = 0; half < 2; half++) {
                int gr = bm + wm*64 + mi*16 + (lane >> 2) + half*8;
                if (gr >= M) continue;
                float v0 = acc[mi][nj][half*2 + 0];
                float v1 = acc[mi][nj][half*2 + 1];
                if (mode == 2) {
                    v0 += bias[gc]; v1 += bias[gc + 1];
                    float g0 = 0.5f * v0 * (1.f + erff(v0 * 0.70710678118654752f));
                    float g1 = 0.5f * v1 * (1.f + erff(v1 * 0.70710678118654752f));
                    __nv_bfloat162 hh, ll;
                    split_bf16(g0, hh.x, ll.x);
                    split_bf16(g1, hh.y, ll.y);
                    *(__nv_bfloat162*)(Oh + (long long)gr*N + gc) = hh;
                    *(__nv_bfloat162*)(Ol + (long long)gr*N + gc) = ll;
                } else {
                    float* Cp = C + (long long)gr*N + gc;
                    if (mode == 1) { Cp[0] += v0; Cp[1] += v1; }
                    else { float2 w = make_float2(v0, v1); *(float2*)Cp = w; }
                }
            }
        }
    }
}

// ---------------- agg finalize ------------------------------------------------
__global__ void agg_fin_kernel(const float* __restrict__ b_rel) {
    long long n = (long long)NN * DIM;
    long long stride = (long long)gridDim.x * blockDim.x;
    for (long long idx = (long long)blockIdx.x*blockDim.x + threadIdx.x; idx < n; idx += stride) {
        int row = (int)(idx >> 9);
        int col = (int)(idx & 511);
        float d0 = g_deg[row], d1 = g_deg[NN + row], d2 = g_deg[2*NN + row], d3 = g_deg[3*NN + row];
        float dsum = d0 + d1 + d2 + d3;
        float inv = 1.f / fmaxf(dsum, 1.f);
        float v = g_agg[idx] + d0*b_rel[col] + d1*b_rel[DIM + col]
                             + d2*b_rel[2*DIM + col] + d3*b_rel[3*DIM + col];
        g_agg[idx] = v * inv;
    }
}

// ---------------- LN1 ---------------------------------------------------------
__global__ void ln1_kernel(const float* __restrict__ b_self, const float* __restrict__ gw,
                           const float* __restrict__ gb) {
    __shared__ float2 red[256];
    int row = blockIdx.x, t = threadIdx.x;
    long long off = (long long)row * DIM;
    float v0 = g_base[off+t]     + g_agg[off+t]     + b_self[t];
    float v1 = g_base[off+t+256] + g_agg[off+t+256] + b_self[t+256];
    red[t] = make_float2(v0 + v1, v0*v0 + v1*v1);
    __syncthreads();
    for (int s = 128; s > 0; s >>= 1) {
        if (t < s) { red[t].x += red[t+s].x; red[t].y += red[t+s].y; }
        __syncthreads();
    }
    float m = red[0].x * (1.f/DIM);
    float var = red[0].y * (1.f/DIM) - m*m;
    float r = rsqrtf(var + 1e-5f);
    float x0 = (v0 - m)*r*gw[t]     + gb[t];
    float x1 = (v1 - m)*r*gw[t+256] + gb[t+256];
    g_x1[off+t] = x0; g_x1[off+t+256] = x1;
    split_bf16(x0, g_x1h[off+t],     g_x1l[off+t]);
    split_bf16(x1, g_x1h[off+t+256], g_x1l[off+t+256]);
}

// ---------------- final fused: LN2 -> out-LN -> graph mix ---------------------
__global__ void final_fuse_kernel(const float* __restrict__ bf2,
                                  const float* __restrict__ n2g, const float* __restrict__ n2b,
                                  const float* __restrict__ og,  const float* __restrict__ ob,
                                  const float* __restrict__ gml, float* __restrict__ out) {
    __shared__ float2 red[256];
    int row = blockIdx.x, t = threadIdx.x;
    long long off = (long long)row * DIM;
    float t0 = g_x1[off+t]     + g_agg[off+t]     + bf2[t];
    float t1 = g_x1[off+t+256] + g_agg[off+t+256] + bf2[t+256];
    red[t] = make_float2(t0 + t1, t0*t0 + t1*t1);
    __syncthreads();
    for (int s = 128; s > 0; s >>= 1) {
        if (t < s) { red[t].x += red[t+s].x; red[t].y += red[t+s].y; }
        __syncthreads();
    }
    float m = red[0].x * (1.f/DIM);
    float var = red[0].y * (1.f/DIM) - m*m;
    float r = rsqrtf(var + 1e-5f);
    float x20 = (t0 - m)*r*n2g[t]     + n2b[t];
    float x21 = (t1 - m)*r*n2g[t+256] + n2b[t+256];
    __syncthreads();
    red[t] = make_float2(x20 + x21, x20*x20 + x21*x21);
    __syncthreads();
    for (int s = 128; s > 0; s >>= 1) {
        if (t < s) { red[t].x += red[t+s].x; red[t].y += red[t+s].y; }
        __syncthreads();
    }
    m = red[0].x * (1.f/DIM);
    var = red[0].y * (1.f/DIM) - m*m;
    r = rsqrtf(var + 1e-5f);
    float x30 = (x20 - m)*r*og[t]     + ob[t];
    float x31 = (x21 - m)*r*og[t+256] + ob[t+256];
    float gm = 1.f / (1.f + expf(-gml[0]));
    float b0 = g_base[off+t], b1 = g_base[off+t+256];
    out[off+t]     = b0 + gm*(x30 - b0);
    out[off+t+256] = b1 + gm*(x31 - b1);
}

// ---------------- pooling -----------------------------------------------------
__global__ void pool_part_kernel(const float* __restrict__ x) {
    int b = blockIdx.x;
    int t = threadIdx.x;
    float s = 0.f;
    for (int r = b; r < NN; r += 256)
        s += x[(long long)r*DIM + t];
    g_part[b*DIM + t] = s;
}

__global__ void pool_final_kernel(const float* __restrict__ x, const float* __restrict__ dml,
                                  float* __restrict__ pooled) {
    int t = threadIdx.x;
    float s = 0.f;
    for (int b = 0; b < 256; ++b) s += g_part[b*DIM + t];
    float mean = s * (1.f / NN);
    float dm = 1.f / (1.f + expf(-dml[0]));
    pooled[t] = dm * x[t] + (1.f - dm) * mean;
}

// ---------------- host launcher ----------------------------------------------
extern "C" void kernel_launch(void* const* d_in, const int* in_sizes, int n_in,
                              void* d_out, int out_size) {
    (void)in_sizes; (void)n_in; (void)out_size;
    const float* nf     = (const float*)d_in[0];
    const void*  ei     = d_in[1];
    const void*  et     = d_in[2];
    const void*  ntype  = d_in[3];
    const float* ew     = (const float*)d_in[4];
    const float* emb    = (const float*)d_in[5];
    const float* W_self = (const float*)d_in[6];
    const float* b_self = (const float*)d_in[7];
    const float* W_rel  = (const float*)d_in[8];
    const float* b_rel  = (const float*)d_in[9];
    const float* in_g   = (const float*)d_in[10];
    const float* in_b   = (const float*)d_in[11];
    const float* n1_g   = (const float*)d_in[12];
    const float* n1_b   = (const float*)d_in[13];
    const float* Wf1    = (const float*)d_in[14];
    const float* bf1    = (const float*)d_in[15];
    const float* Wf2    = (const float*)d_in[16];
    const float* bf2    = (const float*)d_in[17];
    const float* n2_g   = (const float*)d_in[18];
    const float* n2_b   = (const float*)d_in[19];
    const float* out_g  = (const float*)d_in[20];
    const float* out_b  = (const float*)d_in[21];
    const float* gml    = (const float*)d_in[22];
    const float* dml    = (const float*)d_in[23];
    float* out = (float*)d_out;

    static bool init = false;
    static float *p_agg;
    static __nv_bfloat16 *p_sh, *p_sl, *p_bh, *p_bl, *p_x1h, *p_x1l, *p_uh, *p_ul, *p_wh, *p_wl;
    if (!init) {
        cudaGetSymbolAddress((void**)&p_agg, g_agg);
        cudaGetSymbolAddress((void**)&p_sh,  g_sh);
        cudaGetSymbolAddress((void**)&p_sl,  g_sl);
        cudaGetSymbolAddress((void**)&p_bh,  g_baseh);
        cudaGetSymbolAddress((void**)&p_bl,  g_basel);
        cudaGetSymbolAddress((void**)&p_x1h, g_x1h);
        cudaGetSymbolAddress((void**)&p_x1l, g_x1l);
        cudaGetSymbolAddress((void**)&p_uh,  g_uh);
        cudaGetSymbolAddress((void**)&p_ul,  g_ul);
        cudaGetSymbolAddress((void**)&p_wh,  g_wh);
        cudaGetSymbolAddress((void**)&p_wl,  g_wl);
        cudaFuncSetAttribute(gemm_bf16s, cudaFuncAttributeMaxDynamicSharedMemorySize, 65536);
        init = true;
    }

    const int MROWS = (NN + GBM - 1) / GBM;   // 391
    const int SMEMB = 65536;

    detect_idx_kernel<<<1, 256>>>((const unsigned int*)ei);
    zero_kernel<<<1184, 256>>>();
    input_ln_kernel<<<NN, 256>>>(nf, ntype, emb, in_g, in_b);
    conv_w_kernel<<<2048, 256>>>(W_rel,  NRELS*DIM*DIM, WREL_OFF);
    conv_w_kernel<<<512,  256>>>(W_self, DIM*DIM,       WSELF_OFF);
    conv_w_kernel<<<1024, 256>>>(Wf1,    FFDIM*DIM,     WF1_OFF);
    conv_w_kernel<<<1024, 256>>>(Wf2,    DIM*FFDIM,     WF2_OFF);
    scatter_kernel<<<TOTE, 512>>>(ei, et, ew);
    conv_s_kernel<<<4096, 256>>>();

    // agg = sum_r s_r @ W_rel[r].T
    {
        dim3 grid(DIM / GBN, MROWS);
        gemm_bf16s<<<grid, 128, SMEMB>>>(p_sh, p_sl, p_wh + WREL_OFF, p_wl + WREL_OFF,
                                         p_agg, nullptr, nullptr, nullptr,
                                         NN, DIM, DIM, NRELS,
                                         (long long)NN*DIM, (long long)DIM*DIM, 0);
    }
    agg_fin_kernel<<<2048, 256>>>(b_rel);
    // agg += base @ W_self.T
    {
        dim3 grid(DIM / GBN, MROWS);
        gemm_bf16s<<<grid, 128, SMEMB>>>(p_bh, p_bl, p_wh + WSELF_OFF, p_wl + WSELF_OFF,
                                         p_agg, nullptr, nullptr, nullptr,
                                         NN, DIM, DIM, 1, 0, 0, 1);
    }
    ln1_kernel<<<NN, 256>>>(b_self, n1_g, n1_b);

    // FFN1 (+bias+gelu fused, bf16-split output)
    {
        dim3 grid(FFDIM / GBN, MROWS);
        gemm_bf16s<<<grid, 128, SMEMB>>>(p_x1h, p_x1l, p_wh + WF1_OFF, p_wl + WF1_OFF,
                                         nullptr, p_uh, p_ul, bf1,
                                         NN, FFDIM, DIM, 1, 0, 0, 2);
    }
    // FFN2
    {
        dim3 grid(DIM / GBN, MROWS);
        gemm_bf16s<<<grid, 128, SMEMB>>>(p_uh, p_ul, p_wh + WF2_OFF, p_wl + WF2_OFF,
                                         p_agg, nullptr, nullptr, nullptr,
                                         NN, DIM, FFDIM, 1, 0, 0, 0);
    }

    final_fuse_kernel<<<NN, 256>>>(bf2, n2_g, n2_b, out_g, out_b, gml, out);
    pool_part_kernel<<<256, 512>>>(out);
    pool_final_kernel<<<1, 512>>>(out, dml, out + (long long)NN*DIM);
}

// round 6
// speedup vs baseline: 4.8103x; 2.6489x over previous
#include <cuda_runtime.h>
#include <cuda_bf16.h>
#include <math.h>
#include <stdint.h>

#define DIM 512
#define NN 50000
#define NE 100000
#define TOTE (2*NE)
#define NRELS 4
#define FFDIM 1024

// ---------------- scratch (device globals; no allocation allowed) -------------
__device__ __nv_bfloat16 g_yb[NRELS*NN*DIM];    // 204.8 MB per-rel transformed nodes (bf16)
__device__ float g_deg[NN];
__device__ float g_base[NN*DIM];
__device__ __nv_bfloat16 g_baseb[NN*DIM];
__device__ float g_agg[NN*DIM];                 // scatter target / reused as FFN2 out
__device__ float g_self[NN*DIM];
__device__ float g_x1[NN*DIM];
__device__ __nv_bfloat16 g_x1b[NN*DIM];
__device__ __nv_bfloat16 g_ub[NN*FFDIM];        // FFN hidden (post-gelu) bf16
#define NWELEM 2359296
#define WREL_OFF 0
#define WSELF_OFF 1048576
#define WF1_OFF 1310720
#define WF2_OFF 1835008
__device__ __nv_bfloat16 g_wb[NWELEM];
__device__ float g_part[256*DIM];
__device__ int   g_is64;

// ---------------- index dtype detection --------------------------------------
__global__ void detect_idx_kernel(const unsigned int* __restrict__ w) {
    __shared__ int nz;
    if (threadIdx.x == 0) nz = 0;
    __syncthreads();
    int found = 0;
    for (int i = threadIdx.x; i < TOTE/2 * 2; i += blockDim.x) {
        if (w[2*i + 1] != 0u) { found = 1; break; }
        if (2*i + 1 >= TOTE - 1) break;
    }
    if (found) atomicOr(&nz, 1);
    __syncthreads();
    if (threadIdx.x == 0) g_is64 = nz ? 0 : 1;
}

__device__ __forceinline__ int ldidx(const void* p, long long i) {
    return g_is64 ? (int)((const long long*)p)[i] : ((const int*)p)[i];
}

// ---------------- zero agg + deg ----------------------------------------------
__global__ void zero_kernel() {
    long long n4 = (long long)NN*DIM/4;
    float4* s4 = (float4*)g_agg;
    float4 z = make_float4(0.f,0.f,0.f,0.f);
    long long stride = (long long)gridDim.x * blockDim.x;
    for (long long i = (long long)blockIdx.x*blockDim.x + threadIdx.x; i < n4; i += stride)
        s4[i] = z;
    for (int i = blockIdx.x*blockDim.x + threadIdx.x; i < NN; i += (int)stride)
        g_deg[i] = 0.f;
}

// ---------------- input LayerNorm ---------------------------------------------
__global__ void input_ln_kernel(const float* __restrict__ nf, const void* __restrict__ ntype,
                                const float* __restrict__ emb, const float* __restrict__ gw,
                                const float* __restrict__ gb) {
    __shared__ float2 red[256];
    int row = blockIdx.x, t = threadIdx.x;
    int nt = ldidx(ntype, row);
    long long off = (long long)row * DIM;
    float v0 = nf[off + t]       + emb[nt*DIM + t];
    float v1 = nf[off + t + 256] + emb[nt*DIM + t + 256];
    red[t] = make_float2(v0 + v1, v0*v0 + v1*v1);
    __syncthreads();
    for (int s = 128; s > 0; s >>= 1) {
        if (t < s) { red[t].x += red[t+s].x; red[t].y += red[t+s].y; }
        __syncthreads();
    }
    float m = red[0].x * (1.f/DIM);
    float var = red[0].y * (1.f/DIM) - m*m;
    float r = rsqrtf(var + 1e-5f);
    float b0 = (v0 - m)*r*gw[t]     + gb[t];
    float b1 = (v1 - m)*r*gw[t+256] + gb[t+256];
    g_base[off + t]       = b0;
    g_base[off + t + 256] = b1;
    g_baseb[off + t]       = __float2bfloat16(b0);
    g_baseb[off + t + 256] = __float2bfloat16(b1);
}

// ---------------- edge scatter: agg[dst] += w * y[rel][src]; deg[dst] += w ----
__global__ void scatter_kernel(const void* __restrict__ ei, const void* __restrict__ et,
                               const float* __restrict__ ew) {
    int e = blockIdx.x;
    int t = threadIdx.x;   // 0..127, 4 elems each
    int src, dst, rel; float w;
    if (e < NE) {
        src = ldidx(ei, e); dst = ldidx(ei, NE + e);
        rel = ldidx(et, e); w = ew[e];
    } else {
        int e2 = e - NE;
        src = ldidx(ei, NE + e2); dst = ldidx(ei, e2);
        rel = ldidx(et, e2) + 2;  w = ew[e2];
    }
    const uint2* yrow = (const uint2*)(g_yb + ((long long)rel*NN + src)*DIM);
    uint2 pk = yrow[t];
    __nv_bfloat162 p0 = *(__nv_bfloat162*)&pk.x;
    __nv_bfloat162 p1 = *(__nv_bfloat162*)&pk.y;
    float4 v;
    v.x = w * __bfloat162float(p0.x);
    v.y = w * __bfloat162float(p0.y);
    v.z = w * __bfloat162float(p1.x);
    v.w = w * __bfloat162float(p1.y);
    float* p = g_agg + (long long)dst*DIM + t*4;
    asm volatile("red.global.add.v4.f32 [%0], {%1,%2,%3,%4};"
                 :: "l"(p), "f"(v.x), "f"(v.y), "f"(v.z), "f"(v.w) : "memory");
    if (t == 0) atomicAdd(&g_deg[dst], w);
}

// ---------------- weight convert ----------------------------------------------
__global__ void conv_w_kernel(const float* __restrict__ src, int n, int off) {
    for (int i = blockIdx.x*blockDim.x + threadIdx.x; i < n; i += gridDim.x*blockDim.x)
        g_wb[off + i] = __float2bfloat16(src[i]);
}

// ================= bf16 tensor-core GEMM (NT, mma.sync) =======================
// out[z][m,n] = f( sum_k A[m,k]*B[z][n,k] + bias[z][n] )
#define GBM 128
#define GBN 128
#define GBK 32

__device__ __forceinline__ void ldsm4(uint32_t* r, uint32_t addr) {
    asm volatile("ldmatrix.sync.aligned.m8n8.x4.shared.b16 {%0,%1,%2,%3},[%4];\n"
        : "=r"(r[0]), "=r"(r[1]), "=r"(r[2]), "=r"(r[3]) : "r"(addr));
}
__device__ __forceinline__ void mma_bf16(float* d, const uint32_t* a, uint32_t b0, uint32_t b1) {
    asm volatile("mma.sync.aligned.m16n8k16.row.col.f32.bf16.bf16.f32 "
        "{%0,%1,%2,%3},{%4,%5,%6,%7},{%8,%9},{%0,%1,%2,%3};\n"
        : "+f"(d[0]), "+f"(d[1]), "+f"(d[2]), "+f"(d[3])
        : "r"(a[0]), "r"(a[1]), "r"(a[2]), "r"(a[3]), "r"(b0), "r"(b1));
}
__device__ __forceinline__ void cp16(uint32_t dst, const void* src, int sz) {
    asm volatile("cp.async.cg.shared.global [%0],[%1],16,%2;\n" :: "r"(dst), "l"(src), "r"(sz));
}

// mode: 0 = fp32 C = acc (+bias if bias)   1 = bf16 O = acc + bias
//       2 = bf16 O = gelu(acc + bias)
__global__ void __launch_bounds__(128) gemm_bf(
    const __nv_bfloat16* __restrict__ A, const __nv_bfloat16* __restrict__ B,
    float* __restrict__ C, __nv_bfloat16* __restrict__ O, const float* __restrict__ bias,
    int M, int N, int K, long long bStrideZ, long long outStrideZ, long long biasStrideZ, int mode)
{
    extern __shared__ __align__(1024) char smraw[];
    const int tid = threadIdx.x;
    const int lane = tid & 31, wid = tid >> 5;
    const int wm = wid >> 1, wn = wid & 1;
    const int bm = blockIdx.y * GBM, bn = blockIdx.x * GBN, z = blockIdx.z;
    const __nv_bfloat16* Bz = B + (long long)z * bStrideZ;
    const int niter = K / GBK;
    uint32_t smbase = (uint32_t)__cvta_generic_to_shared(smraw);

    float acc[4][8][4];
    #pragma unroll
    for (int i = 0; i < 4; i++)
        #pragma unroll
        for (int j = 0; j < 8; j++)
            #pragma unroll
            for (int c = 0; c < 4; c++) acc[i][j][c] = 0.f;

    auto issue_copy = [&](int stage, int it) {
        int kb = it * GBK;
        #pragma unroll
        for (int i = 0; i < 8; i++) {
            int id  = i * 128 + tid;
            int q   = id >> 9;
            int rem = id & 511;
            int row = rem >> 2, c = rem & 3;
            uint32_t dst = smbase + stage*16384 + q*8192
                         + (uint32_t)(row*64 + ((c ^ ((row>>1)&3)) << 4));
            int sz = 16;
            const __nv_bfloat16* src;
            if (q == 0) {
                int gr = bm + row;
                if (gr >= M) { sz = 0; gr = 0; }
                src = A + (long long)gr*K + kb + c*8;
            } else {
                src = Bz + (long long)(bn + row)*K + kb + c*8;
            }
            cp16(dst, src, sz);
        }
        asm volatile("cp.async.commit_group;\n" ::: "memory");
    };

    issue_copy(0, 0);

    for (int it = 0; it < niter; ++it) {
        if (it + 1 < niter) {
            issue_copy((it + 1) & 1, it + 1);
            asm volatile("cp.async.wait_group 1;\n" ::: "memory");
        } else {
            asm volatile("cp.async.wait_group 0;\n" ::: "memory");
        }
        __syncthreads();

        uint32_t sA = smbase + (it & 1)*16384;
        uint32_t sB = sA + 8192;
        int rsel = lane & 15;
        #pragma unroll
        for (int kk = 0; kk < 2; kk++) {
            int csel = kk*2 + (lane >> 4);
            uint32_t ah[4][4], bh[4][4];
            #pragma unroll
            for (int mi = 0; mi < 4; mi++) {
                int row = wm*64 + mi*16 + rsel;
                uint32_t off = (uint32_t)(row*64 + ((csel ^ ((row>>1)&3)) << 4));
                ldsm4(ah[mi], sA + off);
            }
            #pragma unroll
            for (int p = 0; p < 4; p++) {
                int row = wn*64 + p*16 + rsel;
                uint32_t off = (uint32_t)(row*64 + ((csel ^ ((row>>1)&3)) << 4));
                ldsm4(bh[p], sB + off);
            }
            #pragma unroll
            for (int mi = 0; mi < 4; mi++)
                #pragma unroll
                for (int nj = 0; nj < 8; nj++) {
                    int p = nj >> 1, h = nj & 1;
                    mma_bf16(acc[mi][nj], ah[mi], bh[p][h], bh[p][2+h]);
                }
        }
        __syncthreads();
    }

    // ---- epilogue -----------------------------------------------------------
    #pragma unroll
    for (int mi = 0; mi < 4; mi++) {
        #pragma unroll
        for (int nj = 0; nj < 8; nj++) {
            int gc = bn + wn*64 + nj*8 + (lane & 3)*2;
            #pragma unroll
            for (int half = 0; half < 2; half++) {
                int gr = bm + wm*64 + mi*16 + (lane >> 2) + half*8;
                if (gr >= M) continue;
                float v0 = acc[mi][nj][half*2 + 0];
                float v1 = acc[mi][nj][half*2 + 1];
                if (mode == 0) {
                    if (bias) {
                        const float* bs = bias + (long long)z*biasStrideZ;
                        v0 += bs[gc]; v1 += bs[gc+1];
                    }
                    float* Cp = C + (long long)z*outStrideZ + (long long)gr*N + gc;
                    float2 w2 = make_float2(v0, v1);
                    *(float2*)Cp = w2;
                } else {
                    const float* bs = bias + (long long)z*biasStrideZ;
                    v0 += bs[gc]; v1 += bs[gc+1];
                    if (mode == 2) {
                        v0 = 0.5f * v0 * (1.f + erff(v0 * 0.70710678118654752f));
                        v1 = 0.5f * v1 * (1.f + erff(v1 * 0.70710678118654752f));
                    }
                    __nv_bfloat162 o;
                    o.x = __float2bfloat16(v0);
                    o.y = __float2bfloat16(v1);
                    *(__nv_bfloat162*)(O + (long long)z*outStrideZ + (long long)gr*N + gc) = o;
                }
            }
        }
    }
}

// ---------------- LN1: x1 = LN(base + agg/max(deg,1) + self + b_self) ---------
__global__ void ln1_kernel(const float* __restrict__ b_self, const float* __restrict__ gw,
                           const float* __restrict__ gb) {
    __shared__ float2 red[256];
    int row = blockIdx.x, t = threadIdx.x;
    long long off = (long long)row * DIM;
    float inv = 1.f / fmaxf(g_deg[row], 1.f);
    float v0 = g_base[off+t]     + g_agg[off+t]*inv     + g_self[off+t]     + b_self[t];
    float v1 = g_base[off+t+256] + g_agg[off+t+256]*inv + g_self[off+t+256] + b_self[t+256];
    red[t] = make_float2(v0 + v1, v0*v0 + v1*v1);
    __syncthreads();
    for (int s = 128; s > 0; s >>= 1) {
        if (t < s) { red[t].x += red[t+s].x; red[t].y += red[t+s].y; }
        __syncthreads();
    }
    float m = red[0].x * (1.f/DIM);
    float var = red[0].y * (1.f/DIM) - m*m;
    float r = rsqrtf(var + 1e-5f);
    float x0 = (v0 - m)*r*gw[t]     + gb[t];
    float x1 = (v1 - m)*r*gw[t+256] + gb[t+256];
    g_x1[off+t] = x0; g_x1[off+t+256] = x1;
    g_x1b[off+t]     = __float2bfloat16(x0);
    g_x1b[off+t+256] = __float2bfloat16(x1);
}

// ---------------- final fused: LN2 -> out-LN -> graph mix ---------------------
__global__ void final_fuse_kernel(const float* __restrict__ bf2,
                                  const float* __restrict__ n2g, const float* __restrict__ n2b,
                                  const float* __restrict__ og,  const float* __restrict__ ob,
                                  const float* __restrict__ gml, float* __restrict__ out) {
    __shared__ float2 red[256];
    int row = blockIdx.x, t = threadIdx.x;
    long long off = (long long)row * DIM;
    float t0 = g_x1[off+t]     + g_agg[off+t]     + bf2[t];
    float t1 = g_x1[off+t+256] + g_agg[off+t+256] + bf2[t+256];
    red[t] = make_float2(t0 + t1, t0*t0 + t1*t1);
    __syncthreads();
    for (int s = 128; s > 0; s >>= 1) {
        if (t < s) { red[t].x += red[t+s].x; red[t].y += red[t+s].y; }
        __syncthreads();
    }
    float m = red[0].x * (1.f/DIM);
    float var = red[0].y * (1.f/DIM) - m*m;
    float r = rsqrtf(var + 1e-5f);
    float x20 = (t0 - m)*r*n2g[t]     + n2b[t];
    float x21 = (t1 - m)*r*n2g[t+256] + n2b[t+256];
    __syncthreads();
    red[t] = make_float2(x20 + x21, x20*x20 + x21*x21);
    __syncthreads();
    for (int s = 128; s > 0; s >>= 1) {
        if (t < s) { red[t].x += red[t+s].x; red[t].y += red[t+s].y; }
        __syncthreads();
    }
    m = red[0].x * (1.f/DIM);
    var = red[0].y * (1.f/DIM) - m*m;
    r = rsqrtf(var + 1e-5f);
    float x30 = (x20 - m)*r*og[t]     + ob[t];
    float x31 = (x21 - m)*r*og[t+256] + ob[t+256];
    float gm = 1.f / (1.f + expf(-gml[0]));
    float b0 = g_base[off+t], b1 = g_base[off+t+256];
    out[off+t]     = b0 + gm*(x30 - b0);
    out[off+t+256] = b1 + gm*(x31 - b1);
}

// ---------------- pooling -----------------------------------------------------
__global__ void pool_part_kernel(const float* __restrict__ x) {
    int b = blockIdx.x;
    int t = threadIdx.x;
    float s = 0.f;
    for (int r = b; r < NN; r += 256)
        s += x[(long long)r*DIM + t];
    g_part[b*DIM + t] = s;
}

__global__ void pool_final_kernel(const float* __restrict__ x, const float* __restrict__ dml,
                                  float* __restrict__ pooled) {
    int t = threadIdx.x;
    float s = 0.f;
    for (int b = 0; b < 256; ++b) s += g_part[b*DIM + t];
    float mean = s * (1.f / NN);
    float dm = 1.f / (1.f + expf(-dml[0]));
    pooled[t] = dm * x[t] + (1.f - dm) * mean;
}

// ---------------- host launcher ----------------------------------------------
extern "C" void kernel_launch(void* const* d_in, const int* in_sizes, int n_in,
                              void* d_out, int out_size) {
    (void)in_sizes; (void)n_in; (void)out_size;
    const float* nf     = (const float*)d_in[0];
    const void*  ei     = d_in[1];
    const void*  et     = d_in[2];
    const void*  ntype  = d_in[3];
    const float* ew     = (const float*)d_in[4];
    const float* emb    = (const float*)d_in[5];
    const float* W_self = (const float*)d_in[6];
    const float* b_self = (const float*)d_in[7];
    const float* W_rel  = (const float*)d_in[8];
    const float* b_rel  = (const float*)d_in[9];
    const float* in_g   = (const float*)d_in[10];
    const float* in_b   = (const float*)d_in[11];
    const float* n1_g   = (const float*)d_in[12];
    const float* n1_b   = (const float*)d_in[13];
    const float* Wf1    = (const float*)d_in[14];
    const float* bf1    = (const float*)d_in[15];
    const float* Wf2    = (const float*)d_in[16];
    const float* bf2    = (const float*)d_in[17];
    const float* n2_g   = (const float*)d_in[18];
    const float* n2_b   = (const float*)d_in[19];
    const float* out_g  = (const float*)d_in[20];
    const float* out_b  = (const float*)d_in[21];
    const float* gml    = (const float*)d_in[22];
    const float* dml    = (const float*)d_in[23];
    float* out = (float*)d_out;

    static bool init = false;
    static float *p_agg, *p_self;
    static __nv_bfloat16 *p_yb, *p_bb, *p_x1b, *p_ub, *p_wb;
    if (!init) {
        cudaGetSymbolAddress((void**)&p_yb,   g_yb);
        cudaGetSymbolAddress((void**)&p_agg,  g_agg);
        cudaGetSymbolAddress((void**)&p_self, g_self);
        cudaGetSymbolAddress((void**)&p_bb,   g_baseb);
        cudaGetSymbolAddress((void**)&p_x1b,  g_x1b);
        cudaGetSymbolAddress((void**)&p_ub,   g_ub);
        cudaGetSymbolAddress((void**)&p_wb,   g_wb);
        init = true;
    }

    const int MROWS = (NN + GBM - 1) / GBM;   // 391
    const int SMEMB = 32768;

    detect_idx_kernel<<<1, 256>>>((const unsigned int*)ei);
    zero_kernel<<<1024, 256>>>();
    input_ln_kernel<<<NN, 256>>>(nf, ntype, emb, in_g, in_b);
    conv_w_kernel<<<2048, 256>>>(W_rel,  NRELS*DIM*DIM, WREL_OFF);
    conv_w_kernel<<<512,  256>>>(W_self, DIM*DIM,       WSELF_OFF);
    conv_w_kernel<<<1024, 256>>>(Wf1,    FFDIM*DIM,     WF1_OFF);
    conv_w_kernel<<<1024, 256>>>(Wf2,    DIM*FFDIM,     WF2_OFF);

    // y[rel] = bf16(base @ W_rel[rel].T + b_rel[rel])
    {
        dim3 grid(DIM / GBN, MROWS, NRELS);
        gemm_bf<<<grid, 128, SMEMB>>>(p_bb, p_wb + WREL_OFF, nullptr, p_yb, b_rel,
                                      NN, DIM, DIM, (long long)DIM*DIM,
                                      (long long)NN*DIM, DIM, 1);
    }
    scatter_kernel<<<TOTE, 128>>>(ei, et, ew);
    // self = base @ W_self.T  (fp32)
    {
        dim3 grid(DIM / GBN, MROWS, 1);
        gemm_bf<<<grid, 128, SMEMB>>>(p_bb, p_wb + WSELF_OFF, p_self, nullptr, nullptr,
                                      NN, DIM, DIM, 0, 0, 0, 0);
    }
    ln1_kernel<<<NN, 256>>>(b_self, n1_g, n1_b);

    // FFN1 (+bias+gelu fused, bf16 output)
    {
        dim3 grid(FFDIM / GBN, MROWS, 1);
        gemm_bf<<<grid, 128, SMEMB>>>(p_x1b, p_wb + WF1_OFF, nullptr, p_ub, bf1,
                                      NN, FFDIM, DIM, 0, 0, 0, 2);
    }
    // FFN2 -> g_agg fp32 (bf2 added in final_fuse)
    {
        dim3 grid(DIM / GBN, MROWS, 1);
        gemm_bf<<<grid, 128, SMEMB>>>(p_ub, p_wb + WF2_OFF, p_agg, nullptr, nullptr,
                                      NN, DIM, FFDIM, 0, 0, 0, 0);
    }

    final_fuse_kernel<<<NN, 256>>>(bf2, n2_g, n2_b, out_g, out_b, gml, out);
    pool_part_kernel<<<256, 512>>>(out);
    pool_final_kernel<<<1, 512>>>(out, dml, out + (long long)NN*DIM);
}